// round 8
// baseline (speedup 1.0000x reference)
#include <cuda_runtime.h>
#include <cuda_bf16.h>
#include <cstdint>

// RNN h_t = tanh([x_t,h_{t-1}]@Wc + bc); out = h_T@Wo + bo
// B=4096, T=128, D=128, H=150, O=10.
// mma.sync.m16n8k16 bf16, 3-pass split. 16 warps (512 thr), K-split pairs:
// warps kh0 (kt 0-8) + kh1 (kt 9-17) per (m,n) tile, fp32 SMEM reduction.
// R8: fix kh1 accumulator reset (c[0..2] were carried across timesteps).

#define T_SEQ 128
#define D_IN  128
#define H_HID 150
#define O_OUT 10
#define M_BLK 32
#define NPAD  152            // 19 n8-tiles (wn groups: 5,5,5,4)
#define KT_HALF 9
#define ASTR  296            // row stride in bf16 elems (592 B; ldmatrix conflict-free)
#define ASTRB 592

// SMEM byte offsets
#define SM_AH   0
#define SM_AL   18944                 // +32*592
#define SM_WH   37888                 // +32*592
#define SM_WL   127872                // +152*592
#define SM_BIAS 217856                // +152*592
#define SM_RED  218464                // +152*4
#define SMEM_BYTES 230752             // +3*4096

typedef unsigned int u32;

__device__ __forceinline__ u32 smem_u32(const void* p) {
    u32 a;
    asm("{ .reg .u64 t; cvta.to.shared.u64 t, %1; cvt.u32.u64 %0, t; }" : "=r"(a) : "l"(p));
    return a;
}
__device__ __forceinline__ void ldsm_x4(u32* r, u32 addr) {
    asm volatile("ldmatrix.sync.aligned.m8n8.x4.shared.b16 {%0,%1,%2,%3}, [%4];"
        : "=r"(r[0]), "=r"(r[1]), "=r"(r[2]), "=r"(r[3]) : "r"(addr));
}
__device__ __forceinline__ void ldsm_x2(u32* r, u32 addr) {
    asm volatile("ldmatrix.sync.aligned.m8n8.x2.shared.b16 {%0,%1}, [%2];"
        : "=r"(r[0]), "=r"(r[1]) : "r"(addr));
}
__device__ __forceinline__ void mma16816(float* c, const u32* a, u32 b0, u32 b1) {
    asm volatile("mma.sync.aligned.m16n8k16.row.col.f32.bf16.bf16.f32 "
        "{%0,%1,%2,%3}, {%4,%5,%6,%7}, {%8,%9}, {%0,%1,%2,%3};"
        : "+f"(c[0]), "+f"(c[1]), "+f"(c[2]), "+f"(c[3])
        : "r"(a[0]), "r"(a[1]), "r"(a[2]), "r"(a[3]), "r"(b0), "r"(b1));
}
__device__ __forceinline__ u32 cvt2(float a, float b) {   // pack (lo=a, hi=b)
    u32 r;
    asm("cvt.rn.bf16x2.f32 %0, %1, %2;" : "=r"(r) : "f"(b), "f"(a));
    return r;
}
__device__ __forceinline__ float bfr(float x) {
    return __bfloat162float(__float2bfloat16(x));
}
__device__ __forceinline__ float fast_tanh(float x) {
    float xc = fminf(fmaxf(x, -10.0f), 10.0f);
    float e = __expf(2.0f * xc);
    return __fdividef(e - 1.0f, e + 1.0f);
}

__global__ void __launch_bounds__(512, 1)
rnn_hmma_ks_kernel(const float* __restrict__ X,
                   const float* __restrict__ Wc,
                   const float* __restrict__ bc,
                   const float* __restrict__ Wo,
                   const float* __restrict__ bo,
                   float* __restrict__ out)
{
    extern __shared__ char smem[];
    const u32 sb = smem_u32(smem);
    const int tid  = threadIdx.x;
    const int lane = tid & 31;
    const int warp = tid >> 5;
    const int wn = warp & 3;           // SMSP/n-group
    const int wm = (warp >> 2) & 1;    // m-tile
    const int kh = warp >> 3;          // k-half
    const int ti = tid & 255;          // pair-matched reduction slot
    const long ctaB0 = (long)blockIdx.x * M_BLK;

    // ================= one-time init =================
    for (int i = tid; i < NPAD * ASTR; i += 512) {
        int n = i / ASTR, k = i - n * ASTR;
        float v = (n < H_HID && k < 278) ? Wc[k * H_HID + n] : 0.0f;
        float h = bfr(v);
        u32 off = (u32)n * ASTRB + (u32)k * 2;
        *(__nv_bfloat16*)(smem + SM_WH + off) = __float2bfloat16(h);
        *(__nv_bfloat16*)(smem + SM_WL + off) = __float2bfloat16(v - h);
    }
    for (int n = tid; n < NPAD; n += 512)
        *(float*)(smem + SM_BIAS + n * 4) = (n < H_HID) ? bc[n] : 0.0f;
    for (int i = tid * 16; i < 2 * M_BLK * ASTRB; i += 512 * 16)
        *(float4*)(smem + SM_AH + i) = make_float4(0.f, 0.f, 0.f, 0.f);
    __syncthreads();

    // x loader: kh1 threads (256 of them), each owns (row m, 16 k-values)
    const int xm = ti >> 3;
    const int xk = (ti & 7) * 16;
    const float* Xrow = X + (ctaB0 + xm) * (long)T_SEQ * D_IN + xk;
    const u32 xdstH = (u32)xm * ASTRB + (u32)xk * 2;
    const u32 xdstL = xdstH + (SM_AL - SM_AH);

    if (kh == 1) {     // store x(0)
        float4 v[4];
#pragma unroll
        for (int q = 0; q < 4; q++) v[q] = *(const float4*)(Xrow + 4 * q);
        u32 hh[8], ll[8];
#pragma unroll
        for (int q = 0; q < 4; q++) {
            float hx = bfr(v[q].x), hy = bfr(v[q].y), hz = bfr(v[q].z), hw = bfr(v[q].w);
            hh[2*q] = cvt2(hx, hy); hh[2*q+1] = cvt2(hz, hw);
            ll[2*q] = cvt2(v[q].x - hx, v[q].y - hy);
            ll[2*q+1] = cvt2(v[q].z - hz, v[q].w - hw);
        }
        *(uint4*)(smem + xdstH)      = *(uint4*)&hh[0];
        *(uint4*)(smem + xdstH + 16) = *(uint4*)&hh[4];
        *(uint4*)(smem + xdstL)      = *(uint4*)&ll[0];
        *(uint4*)(smem + xdstL + 16) = *(uint4*)&ll[4];
    }
    __syncthreads();

    // ============ per-lane ldmatrix bases (k offset by kh half) ============
    const int mat = lane >> 3, r8 = lane & 7;
    const u32 kbase = (u32)(kh * KT_HALF) * 32;
    const u32 aBaseH = sb + SM_AH + (u32)(16 * wm + ((mat & 1) << 3) + r8) * ASTRB
                       + (u32)((mat >> 1) << 3) * 2 + kbase;
    const u32 aBaseL = aBaseH + (SM_AL - SM_AH);
    const int nb = 40 * wn;
    const u32 bBase1 = sb + SM_WH + (u32)(nb + ((mat >> 1) << 3) + r8) * ASTRB
                       + (u32)((mat & 1) << 3) * 2 + kbase;
    const u32 bBase2 = bBase1 + 16 * ASTRB;
    const u32 bBase3 = sb + SM_WH + (u32)(nb + 32 + r8) * ASTRB
                       + (u32)((mat & 1) << 3) * 2 + kbase;
    const u32 WLOFF = SM_WL - SM_WH;
    const bool has5 = (wn < 3);        // wn==3 group has only 4 n8-tiles

    // epilogue mapping + hoisted bias
    const int eg = lane >> 2, et2 = (lane & 3) * 2;
    const int em0 = 16 * wm + eg;
    float2 bias_r[5];
#pragma unroll
    for (int j = 0; j < 5; j++) {
        int n = nb + 8 * j + et2;
        bias_r[j] = (j < 4 || has5) ? *(const float2*)(smem + SM_BIAS + n * 4)
                                    : make_float2(0.f, 0.f);
    }

    float4 c[5];
#pragma unroll
    for (int j = 0; j < 5; j++) c[j] = make_float4(0.f, 0.f, 0.f, 0.f);

    // ================= time loop =================
    for (int t = 0; t < T_SEQ; t++) {
        // kh1 prefetches x(t+1)
        float4 v[4];
        const bool havex = (t + 1 < T_SEQ);
        if (kh == 1 && havex) {
            const float* xp = Xrow + (long)(t + 1) * D_IN;
#pragma unroll
            for (int q = 0; q < 4; q++) v[q] = *(const float4*)(xp + 4 * q);
        }

        // ---- K loop: this warp's 9 k-tiles, 3 passes ----
#pragma unroll
        for (int kt = 0; kt < KT_HALF; kt++) {
            const u32 ko = (u32)kt * 32;
            u32 a[4], al[4], bh1[4], bh2[4], bh3[2], bl1[4], bl2[4], bl3[2];
            ldsm_x4(a,   aBaseH + ko);
            ldsm_x4(al,  aBaseL + ko);
            ldsm_x4(bh1, bBase1 + ko);
            ldsm_x4(bh2, bBase2 + ko);
            ldsm_x4(bl1, bBase1 + WLOFF + ko);
            ldsm_x4(bl2, bBase2 + WLOFF + ko);
            if (has5) {
                ldsm_x2(bh3, bBase3 + ko);
                ldsm_x2(bl3, bBase3 + WLOFF + ko);
            }
            mma16816(&c[0].x, a, bh1[0], bh1[1]);
            mma16816(&c[1].x, a, bh1[2], bh1[3]);
            mma16816(&c[2].x, a, bh2[0], bh2[1]);
            mma16816(&c[3].x, a, bh2[2], bh2[3]);
            mma16816(&c[0].x, a, bl1[0], bl1[1]);
            mma16816(&c[1].x, a, bl1[2], bl1[3]);
            mma16816(&c[2].x, a, bl2[0], bl2[1]);
            mma16816(&c[3].x, a, bl2[2], bl2[3]);
            mma16816(&c[0].x, al, bh1[0], bh1[1]);
            mma16816(&c[1].x, al, bh1[2], bh1[3]);
            mma16816(&c[2].x, al, bh2[0], bh2[1]);
            mma16816(&c[3].x, al, bh2[2], bh2[3]);
            if (has5) {
                mma16816(&c[4].x, a,  bh3[0], bh3[1]);
                mma16816(&c[4].x, a,  bl3[0], bl3[1]);
                mma16816(&c[4].x, al, bh3[0], bh3[1]);
            }
        }

        __syncthreads();   // (A) all ldmatrix reads of A done

        // ---- round 1: reduce c[0..2] ----
        if (kh == 1) {
            *(float4*)(smem + SM_RED +        ti * 16) = c[0];
            *(float4*)(smem + SM_RED + 4096 + ti * 16) = c[1];
            *(float4*)(smem + SM_RED + 8192 + ti * 16) = c[2];
            // FIX: kh1 must reset its partial accumulators each timestep
            c[0] = make_float4(0.f, 0.f, 0.f, 0.f);
            c[1] = make_float4(0.f, 0.f, 0.f, 0.f);
            c[2] = make_float4(0.f, 0.f, 0.f, 0.f);
        }
        __syncthreads();   // (B)
        if (kh == 0) {
#pragma unroll
            for (int j = 0; j < 3; j++) {
                float4 p = *(const float4*)(smem + SM_RED + j * 4096 + ti * 16);
                const int n = nb + 8 * j + et2;
                float h00 = fast_tanh(c[j].x + p.x + bias_r[j].x);
                float h01 = fast_tanh(c[j].y + p.y + bias_r[j].y);
                float h10 = fast_tanh(c[j].z + p.z + bias_r[j].x);
                float h11 = fast_tanh(c[j].w + p.w + bias_r[j].y);
                float r00 = bfr(h00), r01 = bfr(h01), r10 = bfr(h10), r11 = bfr(h11);
                u32 o0 = (u32)em0 * ASTRB + (u32)(D_IN + n) * 2;
                u32 o1 = o0 + 8 * ASTRB;
                *(u32*)(smem + SM_AH + o0) = cvt2(h00, h01);
                *(u32*)(smem + SM_AH + o1) = cvt2(h10, h11);
                *(u32*)(smem + SM_AL + o0) = cvt2(h00 - r00, h01 - r01);
                *(u32*)(smem + SM_AL + o1) = cvt2(h10 - r10, h11 - r11);
                c[j] = make_float4(0.f, 0.f, 0.f, 0.f);
            }
        } else if (havex) {   // kh1: store x(t+1) (A x-cols free after sync A)
            u32 hh[8], ll[8];
#pragma unroll
            for (int q = 0; q < 4; q++) {
                float hx = bfr(v[q].x), hy = bfr(v[q].y), hz = bfr(v[q].z), hw = bfr(v[q].w);
                hh[2*q] = cvt2(hx, hy); hh[2*q+1] = cvt2(hz, hw);
                ll[2*q] = cvt2(v[q].x - hx, v[q].y - hy);
                ll[2*q+1] = cvt2(v[q].z - hz, v[q].w - hw);
            }
            *(uint4*)(smem + xdstH)      = *(uint4*)&hh[0];
            *(uint4*)(smem + xdstH + 16) = *(uint4*)&hh[4];
            *(uint4*)(smem + xdstL)      = *(uint4*)&ll[0];
            *(uint4*)(smem + xdstL + 16) = *(uint4*)&ll[4];
        }
        __syncthreads();   // (C) round-1 scratch consumed

        // ---- round 2: reduce c[3..4] ----
        if (kh == 1) {
            *(float4*)(smem + SM_RED +        ti * 16) = c[3];
            if (has5) *(float4*)(smem + SM_RED + 4096 + ti * 16) = c[4];
            c[3] = make_float4(0.f, 0.f, 0.f, 0.f);
            c[4] = make_float4(0.f, 0.f, 0.f, 0.f);
        }
        __syncthreads();   // (D)
        if (kh == 0) {
#pragma unroll
            for (int j = 3; j < 5; j++) {
                if (j == 4 && !has5) break;
                float4 p = *(const float4*)(smem + SM_RED + (j - 3) * 4096 + ti * 16);
                const int n = nb + 8 * j + et2;
                float h00 = fast_tanh(c[j].x + p.x + bias_r[j].x);
                float h01 = fast_tanh(c[j].y + p.y + bias_r[j].y);
                float h10 = fast_tanh(c[j].z + p.z + bias_r[j].x);
                float h11 = fast_tanh(c[j].w + p.w + bias_r[j].y);
                float r00 = bfr(h00), r01 = bfr(h01), r10 = bfr(h10), r11 = bfr(h11);
                u32 o0 = (u32)em0 * ASTRB + (u32)(D_IN + n) * 2;
                u32 o1 = o0 + 8 * ASTRB;
                *(u32*)(smem + SM_AH + o0) = cvt2(h00, h01);
                *(u32*)(smem + SM_AH + o1) = cvt2(h10, h11);
                *(u32*)(smem + SM_AL + o0) = cvt2(h00 - r00, h01 - r01);
                *(u32*)(smem + SM_AL + o1) = cvt2(h10 - r10, h11 - r11);
                c[j] = make_float4(0.f, 0.f, 0.f, 0.f);
            }
        }
        __syncthreads();   // (E) h(t) fully visible
    }

    // ================= classifier head =================
    for (int i = tid; i < M_BLK * O_OUT; i += 512) {
        const int b = i / O_OUT;
        const int o = i - b * O_OUT;
        float s = bo[o];
        const char* rowH = smem + SM_AH + (u32)b * ASTRB + D_IN * 2;
        const char* rowL = smem + SM_AL + (u32)b * ASTRB + D_IN * 2;
#pragma unroll 5
        for (int j = 0; j < H_HID; j++) {
            float hv = __bfloat162float(*(const __nv_bfloat16*)(rowH + 2 * j))
                     + __bfloat162float(*(const __nv_bfloat16*)(rowL + 2 * j));
            s += hv * Wo[j * O_OUT + o];
        }
        out[(ctaB0 + b) * O_OUT + o] = s;
    }
}

extern "C" void kernel_launch(void* const* d_in, const int* in_sizes, int n_in,
                              void* d_out, int out_size)
{
    const float* X  = (const float*)d_in[0];
    const float* Wc = (const float*)d_in[1];
    const float* bc = (const float*)d_in[2];
    const float* Wo = (const float*)d_in[3];
    const float* bo = (const float*)d_in[4];
    float* out = (float*)d_out;

    const int B = in_sizes[0] / (T_SEQ * D_IN);   // 4096

    cudaFuncSetAttribute(rnn_hmma_ks_kernel,
                         cudaFuncAttributeMaxDynamicSharedMemorySize, SMEM_BYTES);

    rnn_hmma_ks_kernel<<<B / M_BLK, 512, SMEM_BYTES>>>(X, Wc, bc, Wo, bo, out);
}